// round 5
// baseline (speedup 1.0000x reference)
#include <cuda_runtime.h>
#include <cstdint>

#define Bq 900
#define Cc 80
#define QC 72000          // Bq*Cc
#define NV4 18000         // QC/4
#define TOPK 300
#define KP 17
#define CAP 2048
#define THRESH 2.5f
#define MAXB 512
#define FT 256            // filter kernel threads
#define FCHUNK 2048       // float4s per filter CTA
#define FCH 9             // ceil(NV4 / FCHUNK)
#define NT2 512           // finish kernel threads

// out layout (floats): labels[B*300] | boxes[B*300*4] | scores[B*300] | kpts[B*300*17*2]

__device__ unsigned long long g_keys[(size_t)MAXB * CAP];   // 8MB scratch
__device__ int g_cnt[MAXB];                                  // zero-init; finish_k re-zeros

__device__ __forceinline__ unsigned long long make_key(float f, int idx) {
    unsigned int u = __float_as_uint(f);
    u = (u & 0x80000000u) ? ~u : (u | 0x80000000u);   // monotone-increasing map
    return ((unsigned long long)u << 32) | (unsigned int)(~idx); // smaller idx -> larger key
}

__device__ __forceinline__ float max4(float4 v) {
    return fmaxf(fmaxf(v.x, v.y), fmaxf(v.z, v.w));
}

__device__ __forceinline__ void emit4g(float4 v, int base,
                                       unsigned long long* keys, int* cnt) {
    if (v.x > THRESH) { int p = atomicAdd(cnt, 1); if (p < CAP) keys[p] = make_key(v.x, base + 0); }
    if (v.y > THRESH) { int p = atomicAdd(cnt, 1); if (p < CAP) keys[p] = make_key(v.y, base + 1); }
    if (v.z > THRESH) { int p = atomicAdd(cnt, 1); if (p < CAP) keys[p] = make_key(v.z, base + 2); }
    if (v.w > THRESH) { int p = atomicAdd(cnt, 1); if (p < CAP) keys[p] = make_key(v.w, base + 3); }
}

// ---------------- Kernel 1: streaming threshold filter ----------------
__global__ __launch_bounds__(FT)
void filter_k(const float* __restrict__ logits) {
    const int row  = blockIdx.y;
    const int base = blockIdx.x * FCHUNK;
    const int tid  = threadIdx.x;
    const float4* lg4 = (const float4*)(logits + (size_t)row * QC);
    unsigned long long* keys = g_keys + (size_t)row * CAP;
    int* cnt = &g_cnt[row];

    if (base + FCHUNK <= NV4) {
        // full chunk: 8 front-batched LDG.128 per thread
        float4 v[8];
        const int i0 = base + tid;
#pragma unroll
        for (int u = 0; u < 8; ++u) v[u] = lg4[i0 + u * FT];
#pragma unroll
        for (int u = 0; u < 8; ++u) {
            if (max4(v[u]) > THRESH) emit4g(v[u], 4 * (i0 + u * FT), keys, cnt);
        }
    } else {
        // ragged last chunk
        for (int i = base + tid; i < NV4; i += FT) {
            float4 v = lg4[i];
            if (max4(v) > THRESH) emit4g(v, 4 * i, keys, cnt);
        }
    }
}

// ---------------- Kernel 2: per-row sort + gather ----------------
__global__ __launch_bounds__(NT2)
void finish_k(const float* __restrict__ logits,
              const float* __restrict__ boxes,
              const float* __restrict__ kpts,
              float* __restrict__ out, int B) {
    __shared__ unsigned long long cand[CAP];   // 16KB; aliased as hist[4096] in fallback
    __shared__ int qbuf[TOPK];
    __shared__ int s_cnt, s_cut, s_n;

    const int tid = threadIdx.x;
    const int b   = blockIdx.x;
    const unsigned long long* keys = g_keys + (size_t)b * CAP;

    int cnt = g_cnt[b];          // every thread reads the same value
    __syncthreads();             // all reads complete before reset
    if (tid == 0) g_cnt[b] = 0;  // restore invariant for next graph replay

    const bool fast = (cnt >= TOPK && cnt <= NT2);

    if (fast) {
        // ---- register bitonic sort, 1 key/thread, n = 512, descending ----
        unsigned long long K = (tid < cnt) ? keys[tid] : 0ULL;
        for (int k = 2; k <= NT2; k <<= 1) {
            bool desc = ((tid & k) == 0);
            for (int j = k >> 1; j > 0; j >>= 1) {
                unsigned long long part;
                if (j >= 32) {
                    __syncthreads();
                    cand[tid] = K;
                    __syncthreads();
                    part = cand[tid ^ j];
                } else {
                    part = __shfl_xor_sync(0xFFFFFFFFu, K, j);
                }
                bool keepMax = (desc == ((tid & j) == 0));
                if (keepMax ? (part > K) : (part < K)) K = part;
            }
        }
        __syncthreads();
        cand[tid] = K;
        __syncthreads();
    } else {
        if (cnt >= TOPK && cnt <= CAP) {
            // mid path: copy candidates to shared
            for (int i = tid; i < cnt; i += NT2) cand[i] = keys[i];
            __syncthreads();
        } else {
            // ---- Fallback (statistically never taken): exact radix-histogram ----
            unsigned int* hist = (unsigned int*)cand;
            for (int i = tid; i < 4096; i += NT2) hist[i] = 0u;
            __syncthreads();
            const float* lg = logits + (size_t)b * QC;
            for (int i = tid; i < QC; i += NT2) {
                unsigned int u = __float_as_uint(lg[i]);
                u = (u & 0x80000000u) ? ~u : (u | 0x80000000u);
                atomicAdd(&hist[u >> 20], 1u);
            }
            __syncthreads();
            if (tid == 0) {
                int acc = 0, cb = 0;
                for (int bin = 4095; bin >= 0; --bin) {
                    acc += (int)hist[bin];
                    if (acc >= TOPK) { cb = bin; break; }
                }
                s_cut = cb;
                s_cnt = 0;
            }
            __syncthreads();       // hist consumed; cand safe to overwrite
            int cut = s_cut;
            for (int i = tid; i < QC; i += NT2) {
                float f = lg[i];
                unsigned int u = __float_as_uint(f);
                u = (u & 0x80000000u) ? ~u : (u | 0x80000000u);
                if ((int)(u >> 20) >= cut) {
                    int p = atomicAdd(&s_cnt, 1);
                    if (p < CAP) cand[p] = make_key(f, i);
                }
            }
            __syncthreads();
            cnt = s_cnt;
            if (cnt > CAP) cnt = CAP;
        }

        // ---- generic shared bitonic sort, descending ----
        if (tid == 0) {
            int n = 1;
            while (n < cnt) n <<= 1;
            s_n = n;
        }
        __syncthreads();
        const int n = s_n;
        for (int i = cnt + tid; i < n; i += NT2) cand[i] = 0ULL;
        __syncthreads();
        for (int k = 2; k <= n; k <<= 1) {
            for (int j = k >> 1; j > 0; j >>= 1) {
                for (int i = tid; i < n; i += NT2) {
                    int ix = i ^ j;
                    if (ix > i) {
                        unsigned long long a = cand[i], c = cand[ix];
                        bool desc = ((i & k) == 0);
                        if (desc ? (a < c) : (a > c)) { cand[i] = c; cand[ix] = a; }
                    }
                }
                __syncthreads();
            }
        }
    }

    // ---- emit labels / scores, stash qidx ----
    const size_t L1 = (size_t)B * TOPK;          // boxes offset
    const size_t L2 = L1 + (size_t)B * TOPK * 4; // scores offset
    const size_t L3 = L2 + (size_t)B * TOPK;     // kpts offset

    if (tid < TOPK) {
        unsigned long long key = cand[tid];
        unsigned int u = (unsigned int)(key >> 32);
        u = (u & 0x80000000u) ? (u & 0x7FFFFFFFu) : ~u;
        float f = __uint_as_float(u);
        int idx = (int)(~(unsigned int)(key & 0xFFFFFFFFu));
        int lab = idx % Cc;
        int q   = idx / Cc;
        qbuf[tid] = q;
        float score = 1.0f / (1.0f + __expf(-f));
        out[(size_t)b * TOPK + tid]      = (float)lab;
        out[L2 + (size_t)b * TOPK + tid] = score;
    }
    __syncthreads();

    // ---- gather boxes (float4) ----
    const float4* bx4 = (const float4*)boxes;
    float4* obx = (float4*)(out + L1);
    if (tid < TOPK) {
        int q = qbuf[tid];
        obx[(size_t)b * TOPK + tid] = bx4[(size_t)b * Bq + q];
    }

    // ---- gather keypoints (float2 per kp) ----
    const float2* kp2 = (const float2*)kpts;
    float2* okp = (float2*)(out + L3);
    for (int i = tid; i < TOPK * KP; i += NT2) {
        int t = i / KP;
        int k = i % KP;
        int q = qbuf[t];
        okp[((size_t)b * TOPK + t) * KP + k] = kp2[((size_t)b * Bq + q) * KP + k];
    }
}

extern "C" void kernel_launch(void* const* d_in, const int* in_sizes, int n_in,
                              void* d_out, int out_size) {
    const float* logits = (const float*)d_in[0];   // [B,900,80]
    const float* boxes  = (const float*)d_in[1];   // [B,900,4]
    const float* kpts   = (const float*)d_in[2];   // [B,900,17,2]
    int B = in_sizes[0] / QC;
    dim3 g1(FCH, B);
    filter_k<<<g1, FT>>>(logits);
    finish_k<<<B, NT2>>>(logits, boxes, kpts, (float*)d_out, B);
}

// round 6
// speedup vs baseline: 1.6250x; 1.6250x over previous
#include <cuda_runtime.h>
#include <cstdint>

#define Bq 900
#define Cc 80
#define QC 72000          // Bq*Cc
#define NV4 18000         // QC/4
#define TOPK 300
#define KP 17
#define NTHREADS 512
#define CAP 2048
#define THRESH 2.5f
#define UNROLL 8

// out layout (floats): labels[B*300] | boxes[B*300*4] | scores[B*300] | kpts[B*300*17*2]

__device__ __forceinline__ unsigned long long make_key(float f, int idx) {
    unsigned int u = __float_as_uint(f);
    u = (u & 0x80000000u) ? ~u : (u | 0x80000000u);   // monotone-increasing map
    return ((unsigned long long)u << 32) | (unsigned int)(~idx); // smaller idx -> larger key
}

__device__ __forceinline__ void emit4(float4 v, int base,
                                      unsigned long long* cand, int* cnt) {
    if (v.x > THRESH) { int p = atomicAdd(cnt, 1); if (p < CAP) cand[p] = make_key(v.x, base + 0); }
    if (v.y > THRESH) { int p = atomicAdd(cnt, 1); if (p < CAP) cand[p] = make_key(v.y, base + 1); }
    if (v.z > THRESH) { int p = atomicAdd(cnt, 1); if (p < CAP) cand[p] = make_key(v.z, base + 2); }
    if (v.w > THRESH) { int p = atomicAdd(cnt, 1); if (p < CAP) cand[p] = make_key(v.w, base + 3); }
}

__device__ __forceinline__ float max4(float4 v) {
    return fmaxf(fmaxf(v.x, v.y), fmaxf(v.z, v.w));
}

__device__ __forceinline__ float4 ldcs4(const float4* p) {
    return __ldcs(p);
}

__global__ __launch_bounds__(NTHREADS, 4)
void dfine_post_kernel(const float* __restrict__ logits,
                       const float* __restrict__ boxes,
                       const float* __restrict__ kpts,
                       float* __restrict__ out, int B) {
    __shared__ unsigned long long cand[CAP];   // 16KB; aliased as hist[4096] in fallback
    __shared__ int qbuf[TOPK];
    __shared__ int s_cnt, s_cut, s_n;

    const int tid = threadIdx.x;
    const int b   = blockIdx.x;

    const float4* lg4 = (const float4*)(logits + (size_t)b * QC);

    if (tid == 0) s_cnt = 0;
    __syncthreads();

    // ---- Pass 1: threshold filter, 8x front-batched LDG.128 (MLP_p1 = 8) ----
    const int NFULL = NV4 / (NTHREADS * UNROLL);     // 4 full outer iters -> 16384 float4s
    for (int it = 0; it < NFULL; ++it) {
        const int i0 = it * NTHREADS * UNROLL + tid;
        float4 v[UNROLL];
#pragma unroll
        for (int u = 0; u < UNROLL; ++u) v[u] = ldcs4(&lg4[i0 + u * NTHREADS]);
#pragma unroll
        for (int u = 0; u < UNROLL; ++u) {
            if (max4(v[u]) > THRESH) emit4(v[u], 4 * (i0 + u * NTHREADS), cand, &s_cnt);
        }
    }
    // tail: remaining float4s (ragged, plain predicated code)
    for (int i = NFULL * NTHREADS * UNROLL + tid; i < NV4; i += NTHREADS) {
        float4 v = ldcs4(&lg4[i]);
        if (max4(v) > THRESH) emit4(v, 4 * i, cand, &s_cnt);
    }
    __syncthreads();
    int cnt = s_cnt;

    // ---- Fallback (statistically never taken): exact radix-histogram select ----
    if (cnt < TOPK || cnt > CAP) {
        unsigned int* hist = (unsigned int*)cand;   // 4096 bins; consumed before cand reused
        for (int i = tid; i < 4096; i += NTHREADS) hist[i] = 0u;
        __syncthreads();
        const float* lg = logits + (size_t)b * QC;
        for (int i = tid; i < QC; i += NTHREADS) {
            unsigned int u = __float_as_uint(lg[i]);
            u = (u & 0x80000000u) ? ~u : (u | 0x80000000u);
            atomicAdd(&hist[u >> 20], 1u);
        }
        __syncthreads();
        if (tid == 0) {
            int acc = 0, cb = 0;
            for (int bin = 4095; bin >= 0; --bin) {
                acc += (int)hist[bin];
                if (acc >= TOPK) { cb = bin; break; }
            }
            s_cut = cb;
            s_cnt = 0;
        }
        __syncthreads();           // hist fully consumed; cand safe to overwrite
        int cut = s_cut;
        for (int i = tid; i < QC; i += NTHREADS) {
            float f = lg[i];
            unsigned int u = __float_as_uint(f);
            u = (u & 0x80000000u) ? ~u : (u | 0x80000000u);
            if ((int)(u >> 20) >= cut) {
                int p = atomicAdd(&s_cnt, 1);
                if (p < CAP) cand[p] = make_key(f, i);
            }
        }
        __syncthreads();
        cnt = s_cnt;
        if (cnt > CAP) cnt = CAP;
    }

    // ---- sort descending ----
    if (cnt <= NTHREADS) {
        // register bitonic: 1 key/thread, n = 512
        unsigned long long K = (tid < cnt) ? cand[tid] : 0ULL;
        for (int k = 2; k <= NTHREADS; k <<= 1) {
            bool desc = ((tid & k) == 0);
            for (int j = k >> 1; j > 0; j >>= 1) {
                unsigned long long part;
                if (j >= 32) {
                    __syncthreads();          // prior stage's reads complete
                    cand[tid] = K;
                    __syncthreads();
                    part = cand[tid ^ j];
                } else {
                    part = __shfl_xor_sync(0xFFFFFFFFu, K, j);
                }
                bool keepMax = (desc == ((tid & j) == 0));
                if (keepMax ? (part > K) : (part < K)) K = part;
            }
        }
        __syncthreads();
        cand[tid] = K;
        __syncthreads();
    } else {
        // generic shared bitonic (rare: cnt in (512, 2048])
        if (tid == 0) {
            int n = 1;
            while (n < cnt) n <<= 1;
            s_n = n;
        }
        __syncthreads();
        const int n = s_n;
        for (int i = cnt + tid; i < n; i += NTHREADS) cand[i] = 0ULL;
        __syncthreads();
        for (int k = 2; k <= n; k <<= 1) {
            for (int j = k >> 1; j > 0; j >>= 1) {
                for (int i = tid; i < n; i += NTHREADS) {
                    int ix = i ^ j;
                    if (ix > i) {
                        unsigned long long a = cand[i], c = cand[ix];
                        bool desc = ((i & k) == 0);
                        if (desc ? (a < c) : (a > c)) { cand[i] = c; cand[ix] = a; }
                    }
                }
                __syncthreads();
            }
        }
    }

    // ---- emit labels / scores, stash qidx ----
    const size_t L1 = (size_t)B * TOPK;          // boxes offset
    const size_t L2 = L1 + (size_t)B * TOPK * 4; // scores offset
    const size_t L3 = L2 + (size_t)B * TOPK;     // kpts offset

    if (tid < TOPK) {
        unsigned long long key = cand[tid];
        unsigned int u = (unsigned int)(key >> 32);
        u = (u & 0x80000000u) ? (u & 0x7FFFFFFFu) : ~u;
        float f = __uint_as_float(u);
        int idx = (int)(~(unsigned int)(key & 0xFFFFFFFFu));
        int lab = idx % Cc;
        int q   = idx / Cc;
        qbuf[tid] = q;
        float score = 1.0f / (1.0f + __expf(-f));
        out[(size_t)b * TOPK + tid]      = (float)lab;
        out[L2 + (size_t)b * TOPK + tid] = score;
    }
    __syncthreads();

    // ---- gather boxes (float4) ----
    const float4* bx4 = (const float4*)boxes;
    float4* obx = (float4*)(out + L1);
    if (tid < TOPK) {
        int q = qbuf[tid];
        obx[(size_t)b * TOPK + tid] = bx4[(size_t)b * Bq + q];
    }

    // ---- gather keypoints (float2 per kp) ----
    const float2* kp2 = (const float2*)kpts;
    float2* okp = (float2*)(out + L3);
    for (int i = tid; i < TOPK * KP; i += NTHREADS) {
        int t = i / KP;
        int k = i % KP;
        int q = qbuf[t];
        okp[((size_t)b * TOPK + t) * KP + k] = kp2[((size_t)b * Bq + q) * KP + k];
    }
}

extern "C" void kernel_launch(void* const* d_in, const int* in_sizes, int n_in,
                              void* d_out, int out_size) {
    const float* logits = (const float*)d_in[0];   // [B,900,80]
    const float* boxes  = (const float*)d_in[1];   // [B,900,4]
    const float* kpts   = (const float*)d_in[2];   // [B,900,17,2]
    int B = in_sizes[0] / QC;
    dfine_post_kernel<<<B, NTHREADS>>>(logits, boxes, kpts, (float*)d_out, B);
}

// round 7
// speedup vs baseline: 1.8472x; 1.1368x over previous
#include <cuda_runtime.h>
#include <cstdint>

#define Bq 900
#define Cc 80
#define QC 72000          // Bq*Cc
#define NV4 18000         // QC/4
#define TOPK 300
#define KP 17
#define NTHREADS 512
#define NWARP 16
#define WSEG 128          // keys per warp segment
#define CAP 2048          // NWARP*WSEG
#define THRESH 2.5f
#define UNROLL 4

// out layout (floats): labels[B*300] | boxes[B*300*4] | scores[B*300] | kpts[B*300*17*2]

__device__ __forceinline__ unsigned long long make_key(float f, int idx) {
    unsigned int u = __float_as_uint(f);
    u = (u & 0x80000000u) ? ~u : (u | 0x80000000u);   // monotone-increasing map
    return ((unsigned long long)u << 32) | (unsigned int)(~idx); // smaller idx -> larger key
}

__device__ __forceinline__ float max4(float4 v) {
    return fmaxf(fmaxf(v.x, v.y), fmaxf(v.z, v.w));
}

__global__ __launch_bounds__(NTHREADS, 4)
void dfine_post_kernel(const float* __restrict__ logits,
                       const float* __restrict__ boxes,
                       const float* __restrict__ kpts,
                       float* __restrict__ out, int B) {
    __shared__ unsigned long long seg[CAP];   // 16KB: 16 warp segments of 128; aliased as
                                              // cand[] for sort and hist[4096] in fallback
    __shared__ int wcnt[NWARP];
    __shared__ int offs[NWARP + 1];
    __shared__ int qbuf[TOPK];
    __shared__ int s_cnt, s_cut, s_n;

    const int tid = threadIdx.x;
    const int wid = tid >> 5;
    const int b   = blockIdx.x;

    const float4* lg4 = (const float4*)(logits + (size_t)b * QC);

    if (tid < NWARP) wcnt[tid] = 0;
    __syncthreads();

    // ---- Pass 1: threshold filter; per-warp segment append (spread-address ATOMS) ----
    int* mycnt = &wcnt[wid];
    unsigned long long* myseg = &seg[wid << 7];
    #define EMIT(val, index) \
        if ((val) > THRESH) { int p = atomicAdd(mycnt, 1); \
            if (p < WSEG) myseg[p] = make_key((val), (index)); }

    const int NFULL = NV4 / (NTHREADS * UNROLL);     // 8 full outer iters
    for (int it = 0; it < NFULL; ++it) {
        const int i0 = it * NTHREADS * UNROLL + tid;
        float4 v[UNROLL];
#pragma unroll
        for (int u = 0; u < UNROLL; ++u) v[u] = lg4[i0 + u * NTHREADS];
#pragma unroll
        for (int u = 0; u < UNROLL; ++u) {
            if (max4(v[u]) > THRESH) {
                int base = 4 * (i0 + u * NTHREADS);
                EMIT(v[u].x, base + 0); EMIT(v[u].y, base + 1);
                EMIT(v[u].z, base + 2); EMIT(v[u].w, base + 3);
            }
        }
    }
    for (int i = NFULL * NTHREADS * UNROLL + tid; i < NV4; i += NTHREADS) {
        float4 v = lg4[i];
        if (max4(v) > THRESH) {
            int base = 4 * i;
            EMIT(v.x, base + 0); EMIT(v.y, base + 1);
            EMIT(v.z, base + 2); EMIT(v.w, base + 3);
        }
    }
    #undef EMIT
    __syncthreads();

    // ---- prefix over warp counts ----
    if (tid == 0) {
        int a = 0, bad = 0;
        for (int w = 0; w < NWARP; ++w) {
            offs[w] = a;
            int c = wcnt[w];
            if (c > WSEG) { bad = 1; c = WSEG; }
            a += c;
        }
        offs[NWARP] = a;
        s_cnt = bad ? -1 : a;
    }
    __syncthreads();
    int cnt = s_cnt;

    const bool fast = (cnt >= TOPK && cnt <= NTHREADS);
    unsigned long long K = 0ULL;

    if (fast) {
        // read my key from segments via offset map (register staging; no compaction)
        if (tid < cnt) {
            int w = 0;
            while (offs[w + 1] <= tid) ++w;
            K = seg[(w << 7) + (tid - offs[w])];
        }
        // ---- register bitonic sort, 1 key/thread, n = 512, descending ----
        for (int k = 2; k <= NTHREADS; k <<= 1) {
            bool desc = ((tid & k) == 0);
            for (int j = k >> 1; j > 0; j >>= 1) {
                unsigned long long part;
                if (j >= 32) {
                    __syncthreads();          // all K reads/prior reads complete
                    seg[tid] = K;
                    __syncthreads();
                    part = seg[tid ^ j];
                } else {
                    part = __shfl_xor_sync(0xFFFFFFFFu, K, j);
                }
                bool keepMax = (desc == ((tid & j) == 0));
                if (keepMax ? (part > K) : (part < K)) K = part;
            }
        }
    } else {
        if (cnt > NTHREADS && cnt <= CAP) {
            // mid path: compact via register staging, then generic shared sort
            unsigned long long r[CAP / NTHREADS];
#pragma unroll
            for (int k = 0; k < CAP / NTHREADS; ++k) {
                int d = tid + k * NTHREADS;
                r[k] = 0ULL;
                if (d < cnt) {
                    int w = 0;
                    while (offs[w + 1] <= d) ++w;
                    r[k] = seg[(w << 7) + (d - offs[w])];
                }
            }
            __syncthreads();
#pragma unroll
            for (int k = 0; k < CAP / NTHREADS; ++k) seg[tid + k * NTHREADS] = r[k];
            __syncthreads();
        } else {
            // ---- Fallback (statistically never taken): exact radix-histogram ----
            unsigned int* hist = (unsigned int*)seg;
            for (int i = tid; i < 4096; i += NTHREADS) hist[i] = 0u;
            __syncthreads();
            const float* lg = logits + (size_t)b * QC;
            for (int i = tid; i < QC; i += NTHREADS) {
                unsigned int u = __float_as_uint(lg[i]);
                u = (u & 0x80000000u) ? ~u : (u | 0x80000000u);
                atomicAdd(&hist[u >> 20], 1u);
            }
            __syncthreads();
            if (tid == 0) {
                int acc = 0, cb = 0;
                for (int bin = 4095; bin >= 0; --bin) {
                    acc += (int)hist[bin];
                    if (acc >= TOPK) { cb = bin; break; }
                }
                s_cut = cb;
                s_cnt = 0;
            }
            __syncthreads();       // hist consumed; seg safe to overwrite
            int cut = s_cut;
            for (int i = tid; i < QC; i += NTHREADS) {
                float f = lg[i];
                unsigned int u = __float_as_uint(f);
                u = (u & 0x80000000u) ? ~u : (u | 0x80000000u);
                if ((int)(u >> 20) >= cut) {
                    int p = atomicAdd(&s_cnt, 1);
                    if (p < CAP) seg[p] = make_key(f, i);
                }
            }
            __syncthreads();
            cnt = s_cnt;
            if (cnt > CAP) cnt = CAP;
        }

        // ---- generic shared bitonic sort, descending ----
        if (tid == 0) {
            int n = 1;
            while (n < cnt) n <<= 1;
            s_n = n;
        }
        __syncthreads();
        const int n = s_n;
        for (int i = cnt + tid; i < n; i += NTHREADS) seg[i] = 0ULL;
        __syncthreads();
        for (int k = 2; k <= n; k <<= 1) {
            for (int j = k >> 1; j > 0; j >>= 1) {
                for (int i = tid; i < n; i += NTHREADS) {
                    int ix = i ^ j;
                    if (ix > i) {
                        unsigned long long a = seg[i], c = seg[ix];
                        bool desc = ((i & k) == 0);
                        if (desc ? (a < c) : (a > c)) { seg[i] = c; seg[ix] = a; }
                    }
                }
                __syncthreads();
            }
        }
        K = seg[tid];   // top-512 in order; only tid<TOPK used below
    }

    // ---- emit labels / scores, stash qidx ----
    const size_t L1 = (size_t)B * TOPK;          // boxes offset
    const size_t L2 = L1 + (size_t)B * TOPK * 4; // scores offset
    const size_t L3 = L2 + (size_t)B * TOPK;     // kpts offset

    if (tid < TOPK) {
        unsigned int u = (unsigned int)(K >> 32);
        u = (u & 0x80000000u) ? (u & 0x7FFFFFFFu) : ~u;
        float f = __uint_as_float(u);
        int idx = (int)(~(unsigned int)(K & 0xFFFFFFFFu));
        int lab = idx % Cc;
        int q   = idx / Cc;
        qbuf[tid] = q;
        float score = 1.0f / (1.0f + __expf(-f));
        out[(size_t)b * TOPK + tid]      = (float)lab;
        out[L2 + (size_t)b * TOPK + tid] = score;
    }
    __syncthreads();

    // ---- gather boxes (float4) ----
    const float4* bx4 = (const float4*)boxes;
    float4* obx = (float4*)(out + L1);
    if (tid < TOPK) {
        int q = qbuf[tid];
        obx[(size_t)b * TOPK + tid] = bx4[(size_t)b * Bq + q];
    }

    // ---- gather keypoints (float2 per kp) ----
    const float2* kp2 = (const float2*)kpts;
    float2* okp = (float2*)(out + L3);
    for (int i = tid; i < TOPK * KP; i += NTHREADS) {
        int t = i / KP;
        int k = i % KP;
        int q = qbuf[t];
        okp[((size_t)b * TOPK + t) * KP + k] = kp2[((size_t)b * Bq + q) * KP + k];
    }
}

extern "C" void kernel_launch(void* const* d_in, const int* in_sizes, int n_in,
                              void* d_out, int out_size) {
    const float* logits = (const float*)d_in[0];   // [B,900,80]
    const float* boxes  = (const float*)d_in[1];   // [B,900,4]
    const float* kpts   = (const float*)d_in[2];   // [B,900,17,2]
    int B = in_sizes[0] / QC;
    dfine_post_kernel<<<B, NTHREADS>>>(logits, boxes, kpts, (float*)d_out, B);
}

// round 8
// speedup vs baseline: 1.8722x; 1.0135x over previous
#include <cuda_runtime.h>
#include <cstdint>

#define Bq 900
#define Cc 80
#define QC 72000          // Bq*Cc
#define NV4H 9000         // float4s per half row
#define TOPK 300
#define KP 17
#define THRESH 2.5f
#define MAXB 512

#define FT 256            // k1 threads
#define FW 8              // k1 warps
#define WSEG 64           // keys per warp segment
#define CAPH 512          // per-half capacity (FW*WSEG)
#define UNROLL 4

#define MT 512            // k2 threads
#define CAP2 2048         // k2 fallback capacity

// out layout (floats): labels[B*300] | boxes[B*300*4] | scores[B*300] | kpts[B*300*17*2]

__device__ unsigned long long g_keys[(size_t)2 * MAXB * CAPH];  // 4MB, rewritten each run
__device__ int g_cnt[2 * MAXB];                                  // rewritten each run

__device__ __forceinline__ unsigned long long make_key(float f, int idx) {
    unsigned int u = __float_as_uint(f);
    u = (u & 0x80000000u) ? ~u : (u | 0x80000000u);   // monotone-increasing map
    return ((unsigned long long)u << 32) | (unsigned int)(~idx); // smaller idx -> larger key
}

__device__ __forceinline__ float max4(float4 v) {
    return fmaxf(fmaxf(v.x, v.y), fmaxf(v.z, v.w));
}

// ---------------- Kernel 1: stream half-row, filter, local sort, coalesced dump ----------------
__global__ __launch_bounds__(FT, 8)
void filter_sort_k(const float* __restrict__ logits) {
    __shared__ unsigned long long seg[CAPH];   // 8 warp segments of 64; reused as sort buffer
    __shared__ int wcnt[FW];
    __shared__ int offs[FW + 1];
    __shared__ int s_tot;

    const int tid  = threadIdx.x;
    const int wid  = tid >> 5;
    const int blk  = blockIdx.x;
    const int row  = blk >> 1;
    const int half = blk & 1;

    const float4* lg4 = (const float4*)(logits + (size_t)row * QC);
    const int i_base = half * NV4H;

    if (tid < FW) wcnt[tid] = 0;
    __syncthreads();

    int* mycnt = &wcnt[wid];
    unsigned long long* myseg = &seg[wid << 6];
    #define EMIT(val, index) \
        if ((val) > THRESH) { int p = atomicAdd(mycnt, 1); \
            if (p < WSEG) myseg[p] = make_key((val), (index)); }

    const int NFULL = NV4H / (FT * UNROLL);          // 8 full iterations (8192 float4s)
    for (int it = 0; it < NFULL; ++it) {
        const int i0 = i_base + it * FT * UNROLL + tid;
        float4 v[UNROLL];
#pragma unroll
        for (int u = 0; u < UNROLL; ++u) v[u] = lg4[i0 + u * FT];
#pragma unroll
        for (int u = 0; u < UNROLL; ++u) {
            if (max4(v[u]) > THRESH) {
                int base = 4 * (i0 + u * FT);
                EMIT(v[u].x, base + 0); EMIT(v[u].y, base + 1);
                EMIT(v[u].z, base + 2); EMIT(v[u].w, base + 3);
            }
        }
    }
    for (int i = i_base + NFULL * FT * UNROLL + tid; i < i_base + NV4H; i += FT) {
        float4 v = lg4[i];
        if (max4(v) > THRESH) {
            int base = 4 * i;
            EMIT(v.x, base + 0); EMIT(v.y, base + 1);
            EMIT(v.z, base + 2); EMIT(v.w, base + 3);
        }
    }
    #undef EMIT
    __syncthreads();

    // prefix over warp counts; detect segment overflow
    if (tid == 0) {
        int a = 0, bad = 0;
        for (int w = 0; w < FW; ++w) {
            offs[w] = a;
            int c = wcnt[w];
            if (c > WSEG) { bad = 1; c = WSEG; }
            a += c;
        }
        offs[FW] = a;
        s_tot = bad ? -1 : a;
        g_cnt[blk] = s_tot;
    }
    __syncthreads();
    int tot = s_tot;
    if (tot < 0) tot = offs[FW];   // still produce data (unused; k2 falls back)

    // compact via register staging (2 slots/thread), then in-place to seg[]
    unsigned long long r0 = 0ULL, r1 = 0ULL;
    {
        int d0 = tid, d1 = tid + FT;
        if (d0 < tot) {
            int w = 0;
            while (offs[w + 1] <= d0) ++w;
            r0 = seg[(w << 6) + (d0 - offs[w])];
        }
        if (d1 < tot) {
            int w = 0;
            while (offs[w + 1] <= d1) ++w;
            r1 = seg[(w << 6) + (d1 - offs[w])];
        }
    }
    __syncthreads();
    seg[tid] = r0;
    seg[tid + FT] = r1;
    __syncthreads();

    // bitonic sort n=512 descending, 256 threads (1 exchange/thread/stage)
    for (int k = 2; k <= CAPH; k <<= 1) {
        for (int j = k >> 1; j > 0; j >>= 1) {
            int i = ((tid & ~(j - 1)) << 1) | (tid & (j - 1));
            int ix = i | j;
            unsigned long long a = seg[i], c = seg[ix];
            bool desc = ((i & k) == 0);
            if (desc ? (a < c) : (a > c)) { seg[i] = c; seg[ix] = a; }
            __syncthreads();
        }
    }

    // coalesced dump of sorted keys
    unsigned long long* dst = g_keys + (size_t)blk * CAPH;
    dst[tid] = seg[tid];
    dst[tid + FT] = seg[tid + FT];
}

// ---------------- Kernel 2: merge two sorted halves, gather, write ----------------
__global__ __launch_bounds__(MT)
void merge_gather_k(const float* __restrict__ logits,
                    const float* __restrict__ boxes,
                    const float* __restrict__ kpts,
                    float* __restrict__ out, int B) {
    __shared__ unsigned long long buf[CAP2];   // [0:512)=A, [512:1024)=B, [1024:1324)=top
                                               // fallback: hist[4096] alias + candidates
    __shared__ int qbuf[TOPK];
    __shared__ int s_cnt, s_cut, s_n;

    const int tid = threadIdx.x;
    const int b   = blockIdx.x;

    int cA = g_cnt[2 * b];
    int cB = g_cnt[2 * b + 1];
    const bool ok = (cA >= 0 && cB >= 0 && cA + cB >= TOPK);

    int topbase = 1024;   // index of top[] region when ok

    if (ok) {
        buf[tid]       = g_keys[(size_t)(2 * b) * CAPH + tid];         // A (tid<512)
        buf[512 + tid] = g_keys[(size_t)(2 * b + 1) * CAPH + tid];     // B
        __syncthreads();
        // merge-path: rank = own index + count of other-list keys greater
        if (tid < cA) {
            unsigned long long x = buf[tid];
            int lo = 0, hi = cB;
            while (lo < hi) { int mid = (lo + hi) >> 1; if (buf[512 + mid] > x) lo = mid + 1; else hi = mid; }
            int r = tid + lo;
            if (r < TOPK) buf[topbase + r] = x;
        }
        if (tid < cB) {
            unsigned long long x = buf[512 + tid];
            int lo = 0, hi = cA;
            while (lo < hi) { int mid = (lo + hi) >> 1; if (buf[mid] > x) lo = mid + 1; else hi = mid; }
            int r = tid + lo;
            if (r < TOPK) buf[topbase + r] = x;
        }
        __syncthreads();
    } else {
        // ---- Fallback (statistically never taken): exact radix-histogram + sort ----
        topbase = 0;
        unsigned int* hist = (unsigned int*)buf;
        for (int i = tid; i < 4096; i += MT) hist[i] = 0u;
        __syncthreads();
        const float* lg = logits + (size_t)b * QC;
        for (int i = tid; i < QC; i += MT) {
            unsigned int u = __float_as_uint(lg[i]);
            u = (u & 0x80000000u) ? ~u : (u | 0x80000000u);
            atomicAdd(&hist[u >> 20], 1u);
        }
        __syncthreads();
        if (tid == 0) {
            int acc = 0, cb = 0;
            for (int bin = 4095; bin >= 0; --bin) {
                acc += (int)hist[bin];
                if (acc >= TOPK) { cb = bin; break; }
            }
            s_cut = cb;
            s_cnt = 0;
        }
        __syncthreads();
        int cut = s_cut;
        for (int i = tid; i < QC; i += MT) {
            float f = lg[i];
            unsigned int u = __float_as_uint(f);
            u = (u & 0x80000000u) ? ~u : (u | 0x80000000u);
            if ((int)(u >> 20) >= cut) {
                int p = atomicAdd(&s_cnt, 1);
                if (p < CAP2) buf[p] = make_key(f, i);
            }
        }
        __syncthreads();
        int cnt = s_cnt;
        if (cnt > CAP2) cnt = CAP2;
        if (tid == 0) {
            int n = 1;
            while (n < cnt) n <<= 1;
            s_n = n;
        }
        __syncthreads();
        const int n = s_n;
        for (int i = cnt + tid; i < n; i += MT) buf[i] = 0ULL;
        __syncthreads();
        for (int k = 2; k <= n; k <<= 1) {
            for (int j = k >> 1; j > 0; j >>= 1) {
                for (int i = tid; i < n; i += MT) {
                    int ix = i ^ j;
                    if (ix > i) {
                        unsigned long long a = buf[i], c = buf[ix];
                        bool desc = ((i & k) == 0);
                        if (desc ? (a < c) : (a > c)) { buf[i] = c; buf[ix] = a; }
                    }
                }
                __syncthreads();
            }
        }
    }

    // ---- emit labels / scores, stash qidx ----
    const size_t L1 = (size_t)B * TOPK;          // boxes offset
    const size_t L2 = L1 + (size_t)B * TOPK * 4; // scores offset
    const size_t L3 = L2 + (size_t)B * TOPK;     // kpts offset

    if (tid < TOPK) {
        unsigned long long key = buf[topbase + tid];
        unsigned int u = (unsigned int)(key >> 32);
        u = (u & 0x80000000u) ? (u & 0x7FFFFFFFu) : ~u;
        float f = __uint_as_float(u);
        int idx = (int)(~(unsigned int)(key & 0xFFFFFFFFu));
        int lab = idx % Cc;
        int q   = idx / Cc;
        qbuf[tid] = q;
        float score = 1.0f / (1.0f + __expf(-f));
        out[(size_t)b * TOPK + tid]      = (float)lab;
        out[L2 + (size_t)b * TOPK + tid] = score;
    }
    __syncthreads();

    // ---- gather boxes (float4) ----
    const float4* bx4 = (const float4*)boxes;
    float4* obx = (float4*)(out + L1);
    if (tid < TOPK) {
        int q = qbuf[tid];
        obx[(size_t)b * TOPK + tid] = bx4[(size_t)b * Bq + q];
    }

    // ---- gather keypoints (float2 per kp) ----
    const float2* kp2 = (const float2*)kpts;
    float2* okp = (float2*)(out + L3);
    for (int i = tid; i < TOPK * KP; i += MT) {
        int t = i / KP;
        int k = i % KP;
        int q = qbuf[t];
        okp[((size_t)b * TOPK + t) * KP + k] = kp2[((size_t)b * Bq + q) * KP + k];
    }
}

extern "C" void kernel_launch(void* const* d_in, const int* in_sizes, int n_in,
                              void* d_out, int out_size) {
    const float* logits = (const float*)d_in[0];   // [B,900,80]
    const float* boxes  = (const float*)d_in[1];   // [B,900,4]
    const float* kpts   = (const float*)d_in[2];   // [B,900,17,2]
    int B = in_sizes[0] / QC;
    filter_sort_k<<<2 * B, FT>>>(logits);
    merge_gather_k<<<B, MT>>>(logits, boxes, kpts, (float*)d_out, B);
}